// round 3
// baseline (speedup 1.0000x reference)
#include <cuda_runtime.h>
#include <math.h>
#include <stdint.h>

#define N_NODES_MAX 100000
#define N_EDGES_MAX 1600000
#define F_IN  128
#define HID   128
#define N_CLS 40

// ---------------- scratch (static device globals: allocation-free) ----------
__device__ __align__(16) float g_dinv[N_NODES_MAX];
__device__ __align__(16) float g_h1 [(size_t)N_NODES_MAX * HID];   // x @ W1
__device__ __align__(16) float g_agg1[(size_t)N_NODES_MAX * HID];  // Agg(h1)
__device__ __align__(16) float g_p2 [(size_t)N_NODES_MAX * N_CLS]; // relu(agg1+b1) @ W2
__device__ __align__(16) float g_agg2[(size_t)N_NODES_MAX * N_CLS];// Agg(p2)
__device__ int g_idx64;  // 1 if edge_index buffer is int64, 0 if int32

// ---------------- edge-index dtype detection --------------------------------
__global__ void detect_init() { g_idx64 = 1; }

// Sample odd 32-bit words within the first 2E words (safe for both layouts).
// int64 data (values in [0,N)): odd words are high halves == 0.
// int32 data: odd words are random node ids -> some nonzero -> flag = 0.
__global__ void detect_scan(const int* __restrict__ ei32, int E) {
    int i = blockIdx.x * blockDim.x + threadIdx.x;   // 1024 threads
    long long stride = (2LL * E) / 1024;
    if (stride < 2) stride = 2;
    long long pos = ((long long)i * stride) | 1LL;   // odd position
    if (pos < 2LL * E && ei32[pos] != 0) g_idx64 = 0;
}

// ---------------- index helpers ----------------------------------------------
__device__ __forceinline__ int load_idx(const void* ei, long long pos, int is64) {
    return is64 ? (int)((const long long*)ei)[pos] : ((const int*)ei)[pos];
}

// ---------------- degree / normalization ------------------------------------
__global__ void deg_init(int n) {
    int i = blockIdx.x * blockDim.x + threadIdx.x;
    if (i < n) g_dinv[i] = 1.0f;  // self loop counts once
}

__global__ void deg_count(const void* __restrict__ ei, int E, int N) {
    int e = blockIdx.x * blockDim.x + threadIdx.x;
    if (e >= E) return;
    int is64 = g_idx64;
    int d = load_idx(ei, (long long)E + e, is64);
    if ((unsigned)d < (unsigned)N) atomicAdd(&g_dinv[d], 1.0f);
}

__global__ void deg_rsqrt(int n) {
    int i = blockIdx.x * blockDim.x + threadIdx.x;
    if (i < n) g_dinv[i] = rsqrtf(g_dinv[i]);  // in place: becomes dinv
}

// ---------------- tiled GEMM: C[M,N] = act(A)[M,K] @ B[K,N] -----------------
#define BM 64
#define BN 64
#define BK 16
template <bool LAYER2>
__global__ void gemm_act(const float* __restrict__ Ain, const float* __restrict__ B,
                         int M, int N, int K, const float* __restrict__ in_bias) {
    const float* A = LAYER2 ? (const float*)g_agg1 : Ain;
    float* C       = LAYER2 ? (float*)g_p2         : (float*)g_h1;

    __shared__ float As[BK][BM + 1];
    __shared__ float Bs[BK][BN];

    int tid = threadIdx.x;          // 256 threads
    int tx = tid & 15;
    int ty = tid >> 4;
    int row0 = blockIdx.y * BM;
    int col0 = blockIdx.x * BN;

    float acc[4][4] = {};

    int ka = tid & 15;
    int ma = tid >> 4;
    int nb = tid & 63;
    int kb = tid >> 6;

    for (int k0 = 0; k0 < K; k0 += BK) {
        #pragma unroll
        for (int j = 0; j < 4; j++) {
            int m  = ma + 16 * j;
            int gm = row0 + m;
            float v = 0.0f;
            if (gm < M) {
                v = A[(size_t)gm * K + k0 + ka];
                if (LAYER2) v = fmaxf(v + in_bias[k0 + ka], 0.0f);
            }
            As[ka][m] = v;
        }
        #pragma unroll
        for (int j = 0; j < 4; j++) {
            int k  = kb + 4 * j;
            int gn = col0 + nb;
            Bs[k][nb] = (gn < N) ? B[(size_t)(k0 + k) * N + gn] : 0.0f;
        }
        __syncthreads();

        #pragma unroll
        for (int kk = 0; kk < BK; kk++) {
            float a[4], b[4];
            #pragma unroll
            for (int i = 0; i < 4; i++) a[i] = As[kk][ty + 16 * i];
            #pragma unroll
            for (int j = 0; j < 4; j++) b[j] = Bs[kk][tx + 16 * j];
            #pragma unroll
            for (int i = 0; i < 4; i++)
                #pragma unroll
                for (int j = 0; j < 4; j++)
                    acc[i][j] += a[i] * b[j];
        }
        __syncthreads();
    }

    #pragma unroll
    for (int i = 0; i < 4; i++) {
        int r = row0 + ty + 16 * i;
        if (r >= M) continue;
        #pragma unroll
        for (int j = 0; j < 4; j++) {
            int c = col0 + tx + 16 * j;
            if (c < N) C[(size_t)r * N + c] = acc[i][j];
        }
    }
}

// ---------------- self-loop init: agg[i,f] = h[i,f] * dinv[i]^2 -------------
template <bool LAYER2>
__global__ void init_self(int n, int F) {
    const float* h = LAYER2 ? (const float*)g_p2 : (const float*)g_h1;
    float* out     = LAYER2 ? (float*)g_agg2     : (float*)g_agg1;
    long long t = (long long)blockIdx.x * blockDim.x + threadIdx.x;
    if (t >= (long long)n * F) return;
    int i = (int)(t / F);
    float di = g_dinv[i];
    out[t] = h[t] * (di * di);
}

// ---------------- edge scatter, F=128 (warp per edge, float4 lanes) ---------
__global__ void edge_agg_f128(const void* __restrict__ ei, int E, int N) {
    long long t = (long long)blockIdx.x * blockDim.x + threadIdx.x;
    int e = (int)(t >> 5);
    if (e >= E) return;
    int lane = (int)(t & 31);
    int is64 = g_idx64;
    int s = load_idx(ei, e, is64);
    int d = load_idx(ei, (long long)E + e, is64);
    if ((unsigned)s >= (unsigned)N || (unsigned)d >= (unsigned)N) return;
    float norm = g_dinv[s] * g_dinv[d];
    float4 v = ((const float4*)(g_h1 + (size_t)s * HID))[lane];
    float* o = g_agg1 + (size_t)d * HID + lane * 4;
    atomicAdd(o + 0, v.x * norm);
    atomicAdd(o + 1, v.y * norm);
    atomicAdd(o + 2, v.z * norm);
    atomicAdd(o + 3, v.w * norm);
}

// ---------------- edge scatter, F=40 (thread per (edge, col)) ---------------
__global__ void edge_agg_f40(const void* __restrict__ ei, int E, int N) {
    long long t = (long long)blockIdx.x * blockDim.x + threadIdx.x;
    if (t >= (long long)E * N_CLS) return;
    int e = (int)(t / N_CLS);
    int c = (int)(t % N_CLS);
    int is64 = g_idx64;
    int s = load_idx(ei, e, is64);
    int d = load_idx(ei, (long long)E + e, is64);
    if ((unsigned)s >= (unsigned)N || (unsigned)d >= (unsigned)N) return;
    float norm = g_dinv[s] * g_dinv[d];
    atomicAdd(g_agg2 + (size_t)d * N_CLS + c, g_p2[(size_t)s * N_CLS + c] * norm);
}

// ---------------- log_softmax over 40 classes (warp per node), adds b2 ------
__global__ void logsoftmax40(const float* __restrict__ b, float* __restrict__ out, int n) {
    long long t = (long long)blockIdx.x * blockDim.x + threadIdx.x;
    int w = (int)(t >> 5);
    if (w >= n) return;
    int lane = (int)(t & 31);

    float z0 = g_agg2[(size_t)w * N_CLS + lane] + b[lane];
    float z1 = (lane < N_CLS - 32)
             ? g_agg2[(size_t)w * N_CLS + lane + 32] + b[lane + 32]
             : -1e30f;

    float m = fmaxf(z0, z1);
    #pragma unroll
    for (int o = 16; o; o >>= 1) m = fmaxf(m, __shfl_xor_sync(0xFFFFFFFFu, m, o));

    float s = expf(z0 - m) + ((lane < N_CLS - 32) ? expf(z1 - m) : 0.0f);
    #pragma unroll
    for (int o = 16; o; o >>= 1) s += __shfl_xor_sync(0xFFFFFFFFu, s, o);

    float lse = m + logf(s);
    out[(size_t)w * N_CLS + lane] = z0 - lse;
    if (lane < N_CLS - 32) out[(size_t)w * N_CLS + lane + 32] = z1 - lse;
}

// ---------------- launcher ---------------------------------------------------
extern "C" void kernel_launch(void* const* d_in, const int* in_sizes, int n_in,
                              void* d_out, int out_size) {
    const float* x  = (const float*)d_in[0];
    const void*  ei = d_in[1];                 // [2, E]; dtype detected on device
    const float* W1 = (const float*)d_in[2];
    const float* b1 = (const float*)d_in[3];
    const float* W2 = (const float*)d_in[4];
    const float* b2 = (const float*)d_in[5];
    float* out = (float*)d_out;

    int N = in_sizes[0] / F_IN;
    int E = in_sizes[1] / 2;
    if (N > N_NODES_MAX) N = N_NODES_MAX;
    if (E > N_EDGES_MAX) E = N_EDGES_MAX;

    const int TB = 256;

    // 0. detect index dtype (int32 vs int64)
    detect_init<<<1, 1>>>();
    detect_scan<<<4, 256>>>((const int*)ei, E);

    // 1. degree + dinv
    deg_init <<<(N + TB - 1) / TB, TB>>>(N);
    deg_count<<<(E + TB - 1) / TB, TB>>>(ei, E, N);
    deg_rsqrt<<<(N + TB - 1) / TB, TB>>>(N);

    // 2. h1 = x @ W1
    {
        dim3 grid((HID + BN - 1) / BN, (N + BM - 1) / BM);
        gemm_act<false><<<grid, TB>>>(x, W1, N, HID, F_IN, nullptr);
    }

    // 3. agg1 = self-loop term + scatter-add over edges
    {
        long long tot = (long long)N * HID;
        init_self<false><<<(unsigned)((tot + TB - 1) / TB), TB>>>(N, HID);
        long long et = (long long)E * 32;
        edge_agg_f128<<<(unsigned)((et + TB - 1) / TB), TB>>>(ei, E, N);
    }

    // 4. p2 = relu(agg1 + b1) @ W2   (project to 40 dims BEFORE aggregating)
    {
        dim3 grid((N_CLS + BN - 1) / BN, (N + BM - 1) / BM);
        gemm_act<true><<<grid, TB>>>(nullptr, W2, N, N_CLS, HID, b1);
    }

    // 5. agg2 = self-loop term + scatter-add over edges (40 floats/edge)
    {
        long long tot = (long long)N * N_CLS;
        init_self<true><<<(unsigned)((tot + TB - 1) / TB), TB>>>(N, N_CLS);
        long long et = (long long)E * N_CLS;
        edge_agg_f40<<<(unsigned)((et + TB - 1) / TB), TB>>>(ei, E, N);
    }

    // 6. out = log_softmax(agg2 + b2)
    {
        long long t = (long long)N * 32;
        logsoftmax40<<<(unsigned)((t + TB - 1) / TB), TB>>>(b2, out, N);
    }
}

// round 4
// speedup vs baseline: 2.6922x; 2.6922x over previous
#include <cuda_runtime.h>
#include <math.h>
#include <stdint.h>

#define N_NODES_MAX 100000
#define N_EDGES_MAX 1600000
#define F_IN  128
#define HID   128
#define N_CLS 40
#define SCAN_B 1024

// ---------------- scratch (static device globals) ---------------------------
__device__ __align__(16) float g_dinv[N_NODES_MAX];
__device__ __align__(16) float g_h1 [(size_t)N_NODES_MAX * HID];   // x @ W1
__device__ __align__(16) float g_agg1[(size_t)N_NODES_MAX * HID];  // Agg(h1)
__device__ __align__(16) float g_p2 [(size_t)N_NODES_MAX * N_CLS]; // relu(agg1+b1) @ W2
__device__ int   g_cnt[N_NODES_MAX];          // in-degree counts
__device__ int   g_cursor[N_NODES_MAX];       // CSR fill cursors
__device__ int   g_rowstart[N_NODES_MAX + 1]; // CSR row offsets
__device__ int   g_bsum[128];                 // scan partials
__device__ int   g_boff[128];
__device__ int   g_csr_src [N_EDGES_MAX];     // src sorted by dst
__device__ float g_csr_norm[N_EDGES_MAX];     // dinv[s]*dinv[d] per edge
__device__ int   g_idx64;                     // edge_index dtype flag

// ---------------- edge-index dtype detection --------------------------------
__global__ void detect_init() { g_idx64 = 1; }
__global__ void detect_scan(const int* __restrict__ ei32, int E) {
    int i = blockIdx.x * blockDim.x + threadIdx.x;   // 1024 threads
    long long stride = (2LL * E) / 1024;
    if (stride < 2) stride = 2;
    long long pos = ((long long)i * stride) | 1LL;   // odd 32-bit word
    if (pos < 2LL * E && ei32[pos] != 0) g_idx64 = 0;
}
__device__ __forceinline__ int load_idx(const void* ei, long long pos, int is64) {
    return is64 ? (int)((const long long*)ei)[pos] : ((const int*)ei)[pos];
}

// ---------------- CSR build --------------------------------------------------
__global__ void zero_cnt(int n) {
    int i = blockIdx.x * blockDim.x + threadIdx.x;
    if (i < n) { g_cnt[i] = 0; g_cursor[i] = 0; }
}

__global__ void deg_count(const void* __restrict__ ei, int E, int N) {
    int e = blockIdx.x * blockDim.x + threadIdx.x;
    if (e >= E) return;
    int is64 = g_idx64;
    int d = load_idx(ei, (long long)E + e, is64);
    if ((unsigned)d < (unsigned)N) atomicAdd(&g_cnt[d], 1);
}

__global__ void make_dinv(int n) {
    int i = blockIdx.x * blockDim.x + threadIdx.x;
    if (i < n) g_dinv[i] = rsqrtf(1.0f + (float)g_cnt[i]);  // +1 self loop
}

// exclusive scan of g_cnt into g_rowstart (3 kernels)
__global__ void scan1(int n) {
    __shared__ int sh[SCAN_B];
    int t = threadIdx.x, b = blockIdx.x;
    int i = b * SCAN_B + t;
    int v = (i < n) ? g_cnt[i] : 0;
    sh[t] = v;
    __syncthreads();
    for (int o = 1; o < SCAN_B; o <<= 1) {
        int x = (t >= o) ? sh[t - o] : 0;
        __syncthreads();
        sh[t] += x;
        __syncthreads();
    }
    if (i < n) g_rowstart[i] = sh[t] - v;      // exclusive within block
    if (t == SCAN_B - 1) g_bsum[b] = sh[t];
}
__global__ void scan2(int nb) {
    __shared__ int sh[SCAN_B];
    int t = threadIdx.x;
    int v = (t < nb) ? g_bsum[t] : 0;
    sh[t] = v;
    __syncthreads();
    for (int o = 1; o < SCAN_B; o <<= 1) {
        int x = (t >= o) ? sh[t - o] : 0;
        __syncthreads();
        sh[t] += x;
        __syncthreads();
    }
    if (t < nb) g_boff[t] = sh[t] - v;         // exclusive block offsets
}
__global__ void scan3(int n, int E) {
    int i = blockIdx.x * blockDim.x + threadIdx.x;
    if (i < n) g_rowstart[i] += g_boff[i / SCAN_B];
    if (i == 0) g_rowstart[n] = E;
}

__global__ void csr_fill(const void* __restrict__ ei, int E, int N) {
    int e = blockIdx.x * blockDim.x + threadIdx.x;
    if (e >= E) return;
    int is64 = g_idx64;
    int s = load_idx(ei, e, is64);
    int d = load_idx(ei, (long long)E + e, is64);
    if ((unsigned)s >= (unsigned)N || (unsigned)d >= (unsigned)N) return;
    int pos = g_rowstart[d] + atomicAdd(&g_cursor[d], 1);
    g_csr_src[pos]  = s;
    g_csr_norm[pos] = g_dinv[s] * g_dinv[d];
}

// ---------------- GEMM1: g_h1 = x @ W1 (M x 128 x 128), 128x128x16 tile -----
__global__ __launch_bounds__(256) void gemm1(const float* __restrict__ A,
                                             const float* __restrict__ B, int M) {
    __shared__ float As[16][128];
    __shared__ float Bs[16][128];
    int tid = threadIdx.x;
    int tx = tid & 15, ty = tid >> 4;
    int row0 = blockIdx.x * 128;
    float acc[8][8] = {};

    for (int k0 = 0; k0 < 128; k0 += 16) {
        #pragma unroll
        for (int r = 0; r < 2; r++) {                 // A: 2 float4 / thread
            int lin = tid + r * 256;                  // 0..511
            int m = lin & 127;
            int kg = lin >> 7;                        // 0..3
            int gm = row0 + m;
            float4 v = make_float4(0.f, 0.f, 0.f, 0.f);
            if (gm < M) v = *(const float4*)(A + (size_t)gm * 128 + k0 + kg * 4);
            As[kg * 4 + 0][m] = v.x; As[kg * 4 + 1][m] = v.y;
            As[kg * 4 + 2][m] = v.z; As[kg * 4 + 3][m] = v.w;
        }
        #pragma unroll
        for (int r = 0; r < 2; r++) {                 // B: 2 float4 / thread
            int lin = tid + r * 256;
            int k = lin >> 5;                         // 0..15
            int nq = lin & 31;
            *(float4*)&Bs[k][nq * 4] =
                *(const float4*)(B + (size_t)(k0 + k) * 128 + nq * 4);
        }
        __syncthreads();

        #pragma unroll
        for (int kk = 0; kk < 16; kk++) {
            float a[8], b[8];
            #pragma unroll
            for (int i = 0; i < 8; i++) a[i] = As[kk][ty + 16 * i];
            #pragma unroll
            for (int j = 0; j < 8; j++) b[j] = Bs[kk][tx + 16 * j];
            #pragma unroll
            for (int i = 0; i < 8; i++)
                #pragma unroll
                for (int j = 0; j < 8; j++)
                    acc[i][j] += a[i] * b[j];
        }
        __syncthreads();
    }

    #pragma unroll
    for (int i = 0; i < 8; i++) {
        int gm = row0 + ty + 16 * i;
        if (gm >= M) continue;
        #pragma unroll
        for (int j = 0; j < 8; j++)
            g_h1[(size_t)gm * 128 + tx + 16 * j] = acc[i][j];
    }
}

// ---------------- GEMM2: g_p2 = relu(g_agg1 + b1) @ W2 (M x 40 x 128) -------
#define BM 64
#define BN 64
#define BK 16
__global__ __launch_bounds__(256) void gemm2(const float* __restrict__ B,
                                             int M, int N, int K,
                                             const float* __restrict__ in_bias) {
    __shared__ float As[BK][BM + 1];
    __shared__ float Bs[BK][BN];

    int tid = threadIdx.x;
    int tx = tid & 15, ty = tid >> 4;
    int row0 = blockIdx.y * BM;
    int col0 = blockIdx.x * BN;
    float acc[4][4] = {};

    int ka = tid & 15, ma = tid >> 4;
    int nb = tid & 63, kb = tid >> 6;

    for (int k0 = 0; k0 < K; k0 += BK) {
        #pragma unroll
        for (int j = 0; j < 4; j++) {
            int m = ma + 16 * j, gm = row0 + m;
            float v = 0.0f;
            if (gm < M)
                v = fmaxf(g_agg1[(size_t)gm * K + k0 + ka] + in_bias[k0 + ka], 0.0f);
            As[ka][m] = v;
        }
        #pragma unroll
        for (int j = 0; j < 4; j++) {
            int k = kb + 4 * j, gn = col0 + nb;
            Bs[k][nb] = (gn < N) ? B[(size_t)(k0 + k) * N + gn] : 0.0f;
        }
        __syncthreads();
        #pragma unroll
        for (int kk = 0; kk < BK; kk++) {
            float a[4], b[4];
            #pragma unroll
            for (int i = 0; i < 4; i++) a[i] = As[kk][ty + 16 * i];
            #pragma unroll
            for (int j = 0; j < 4; j++) b[j] = Bs[kk][tx + 16 * j];
            #pragma unroll
            for (int i = 0; i < 4; i++)
                #pragma unroll
                for (int j = 0; j < 4; j++)
                    acc[i][j] += a[i] * b[j];
        }
        __syncthreads();
    }
    #pragma unroll
    for (int i = 0; i < 4; i++) {
        int r = row0 + ty + 16 * i;
        if (r >= M) continue;
        #pragma unroll
        for (int j = 0; j < 4; j++) {
            int c = col0 + tx + 16 * j;
            if (c < N) g_p2[(size_t)r * N + c] = acc[i][j];
        }
    }
}

// ---------------- agg1: warp-per-node CSR gather, F=128 ---------------------
__global__ void agg_f128(int N) {
    int warp = (blockIdx.x * blockDim.x + threadIdx.x) >> 5;
    if (warp >= N) return;
    int lane = threadIdx.x & 31;

    float di = g_dinv[warp];
    float4 acc = ((const float4*)(g_h1 + (size_t)warp * HID))[lane];
    float sq = di * di;
    acc.x *= sq; acc.y *= sq; acc.z *= sq; acc.w *= sq;   // self-loop term

    int js = g_rowstart[warp], je = g_rowstart[warp + 1];
    for (int j0 = js; j0 < je; j0 += 32) {
        int rem = je - j0;
        int src = 0; float nrm = 0.0f;
        if (lane < rem) { src = g_csr_src[j0 + lane]; nrm = g_csr_norm[j0 + lane]; }
        int cnt = rem < 32 ? rem : 32;
        int k = 0;
        for (; k + 4 <= cnt; k += 4) {                    // 4-deep MLP
            int s0 = __shfl_sync(0xFFFFFFFFu, src, k + 0);
            int s1 = __shfl_sync(0xFFFFFFFFu, src, k + 1);
            int s2 = __shfl_sync(0xFFFFFFFFu, src, k + 2);
            int s3 = __shfl_sync(0xFFFFFFFFu, src, k + 3);
            float n0 = __shfl_sync(0xFFFFFFFFu, nrm, k + 0);
            float n1 = __shfl_sync(0xFFFFFFFFu, nrm, k + 1);
            float n2 = __shfl_sync(0xFFFFFFFFu, nrm, k + 2);
            float n3 = __shfl_sync(0xFFFFFFFFu, nrm, k + 3);
            float4 v0 = ((const float4*)(g_h1 + (size_t)s0 * HID))[lane];
            float4 v1 = ((const float4*)(g_h1 + (size_t)s1 * HID))[lane];
            float4 v2 = ((const float4*)(g_h1 + (size_t)s2 * HID))[lane];
            float4 v3 = ((const float4*)(g_h1 + (size_t)s3 * HID))[lane];
            acc.x += v0.x*n0 + v1.x*n1 + v2.x*n2 + v3.x*n3;
            acc.y += v0.y*n0 + v1.y*n1 + v2.y*n2 + v3.y*n3;
            acc.z += v0.z*n0 + v1.z*n1 + v2.z*n2 + v3.z*n3;
            acc.w += v0.w*n0 + v1.w*n1 + v2.w*n2 + v3.w*n3;
        }
        for (; k < cnt; k++) {
            int   s = __shfl_sync(0xFFFFFFFFu, src, k);
            float n = __shfl_sync(0xFFFFFFFFu, nrm, k);
            float4 v = ((const float4*)(g_h1 + (size_t)s * HID))[lane];
            acc.x += v.x*n; acc.y += v.y*n; acc.z += v.z*n; acc.w += v.w*n;
        }
    }
    ((float4*)(g_agg1 + (size_t)warp * HID))[lane] = acc;
}

// ---------------- agg2 + log_softmax fused: F=40, warp-per-node -------------
__global__ void agg_f40_lsm(const float* __restrict__ b2, float* __restrict__ out, int N) {
    int warp = (blockIdx.x * blockDim.x + threadIdx.x) >> 5;
    if (warp >= N) return;
    int lane = threadIdx.x & 31;

    float di = g_dinv[warp];
    float sq = di * di;
    const float* prow = g_p2 + (size_t)warp * N_CLS;
    float a0 = prow[lane] * sq;                                  // feature lane
    float a1 = (lane < 8) ? prow[lane + 32] * sq : 0.0f;         // feature lane+32

    int js = g_rowstart[warp], je = g_rowstart[warp + 1];
    for (int j0 = js; j0 < je; j0 += 32) {
        int rem = je - j0;
        int src = 0; float nrm = 0.0f;
        if (lane < rem) { src = g_csr_src[j0 + lane]; nrm = g_csr_norm[j0 + lane]; }
        int cnt = rem < 32 ? rem : 32;
        int k = 0;
        for (; k + 4 <= cnt; k += 4) {
            int s0 = __shfl_sync(0xFFFFFFFFu, src, k + 0);
            int s1 = __shfl_sync(0xFFFFFFFFu, src, k + 1);
            int s2 = __shfl_sync(0xFFFFFFFFu, src, k + 2);
            int s3 = __shfl_sync(0xFFFFFFFFu, src, k + 3);
            float n0 = __shfl_sync(0xFFFFFFFFu, nrm, k + 0);
            float n1 = __shfl_sync(0xFFFFFFFFu, nrm, k + 1);
            float n2 = __shfl_sync(0xFFFFFFFFu, nrm, k + 2);
            float n3 = __shfl_sync(0xFFFFFFFFu, nrm, k + 3);
            const float* r0 = g_p2 + (size_t)s0 * N_CLS;
            const float* r1 = g_p2 + (size_t)s1 * N_CLS;
            const float* r2 = g_p2 + (size_t)s2 * N_CLS;
            const float* r3 = g_p2 + (size_t)s3 * N_CLS;
            a0 += r0[lane]*n0 + r1[lane]*n1 + r2[lane]*n2 + r3[lane]*n3;
            if (lane < 8)
                a1 += r0[lane+32]*n0 + r1[lane+32]*n1 + r2[lane+32]*n2 + r3[lane+32]*n3;
        }
        for (; k < cnt; k++) {
            int   s = __shfl_sync(0xFFFFFFFFu, src, k);
            float n = __shfl_sync(0xFFFFFFFFu, nrm, k);
            const float* r = g_p2 + (size_t)s * N_CLS;
            a0 += r[lane] * n;
            if (lane < 8) a1 += r[lane + 32] * n;
        }
    }

    // log_softmax over 40 classes
    float z0 = a0 + b2[lane];
    float z1 = (lane < 8) ? a1 + b2[lane + 32] : -1e30f;
    float m = fmaxf(z0, z1);
    #pragma unroll
    for (int o = 16; o; o >>= 1) m = fmaxf(m, __shfl_xor_sync(0xFFFFFFFFu, m, o));
    float s = expf(z0 - m) + ((lane < 8) ? expf(z1 - m) : 0.0f);
    #pragma unroll
    for (int o = 16; o; o >>= 1) s += __shfl_xor_sync(0xFFFFFFFFu, s, o);
    float lse = m + logf(s);
    out[(size_t)warp * N_CLS + lane] = z0 - lse;
    if (lane < 8) out[(size_t)warp * N_CLS + lane + 32] = z1 - lse;
}

// ---------------- launcher ---------------------------------------------------
extern "C" void kernel_launch(void* const* d_in, const int* in_sizes, int n_in,
                              void* d_out, int out_size) {
    const float* x  = (const float*)d_in[0];
    const void*  ei = d_in[1];
    const float* W1 = (const float*)d_in[2];
    const float* b1 = (const float*)d_in[3];
    const float* W2 = (const float*)d_in[4];
    const float* b2 = (const float*)d_in[5];
    float* out = (float*)d_out;

    int N = in_sizes[0] / F_IN;
    int E = in_sizes[1] / 2;
    if (N > N_NODES_MAX) N = N_NODES_MAX;
    if (E > N_EDGES_MAX) E = N_EDGES_MAX;

    const int TB = 256;
    int nb = (N + SCAN_B - 1) / SCAN_B;

    // 0. dtype detect
    detect_init<<<1, 1>>>();
    detect_scan<<<4, 256>>>((const int*)ei, E);

    // 1. CSR build (counts -> dinv -> scan -> fill with precomputed norms)
    zero_cnt <<<(N + TB - 1) / TB, TB>>>(N);
    deg_count<<<(E + TB - 1) / TB, TB>>>(ei, E, N);
    make_dinv<<<(N + TB - 1) / TB, TB>>>(N);
    scan1<<<nb, SCAN_B>>>(N);
    scan2<<<1, SCAN_B>>>(nb);
    scan3<<<(N + TB - 1) / TB, TB>>>(N, E);
    csr_fill<<<(E + TB - 1) / TB, TB>>>(ei, E, N);

    // 2. h1 = x @ W1   (overlaps nothing but is independent of CSR until agg)
    gemm1<<<(N + 127) / 128, 256>>>(x, W1, N);

    // 3. agg1 = Â h1  (atomic-free, warp per node, self-loop fused)
    agg_f128<<<(N * 32 + TB - 1) / TB, TB>>>(N);

    // 4. p2 = relu(agg1 + b1) @ W2  (project to 40 before aggregating)
    {
        dim3 grid((N_CLS + BN - 1) / BN, (N + BM - 1) / BM);
        gemm2<<<grid, TB>>>(W2, N, N_CLS, HID, b1);
    }

    // 5. out = log_softmax(Â p2 + b2)   (aggregation + softmax fused)
    agg_f40_lsm<<<(N * 32 + TB - 1) / TB, TB>>>(b2, out, N);
}

// round 5
// speedup vs baseline: 2.7792x; 1.0323x over previous
#include <cuda_runtime.h>
#include <math.h>
#include <stdint.h>

#define N_NODES_MAX 100000
#define N_EDGES_MAX 1600000
#define F_IN  128
#define HID   128
#define N_CLS 40
#define SCAN_B 1024

// ---------------- scratch (static device globals) ---------------------------
__device__ __align__(16) float g_dinv[N_NODES_MAX];
__device__ __align__(16) float g_h1 [(size_t)N_NODES_MAX * HID];   // x @ W1
__device__ __align__(16) float g_agg1[(size_t)N_NODES_MAX * HID];  // Agg(h1)
__device__ __align__(16) float g_p2 [(size_t)N_NODES_MAX * N_CLS]; // relu(agg1+b1) @ W2
__device__ int   g_cnt[N_NODES_MAX];
__device__ int   g_cursor[N_NODES_MAX];
__device__ int   g_rowstart[N_NODES_MAX + 1];
__device__ int   g_bsum[128];
__device__ int   g_boff[128];
__device__ int   g_csr_src[N_EDGES_MAX];      // src sorted by dst
__device__ int   g_idx64;

// ---------------- edge-index dtype detection --------------------------------
__global__ void detect_init() { g_idx64 = 1; }
__global__ void detect_scan(const int* __restrict__ ei32, int E) {
    int i = blockIdx.x * blockDim.x + threadIdx.x;
    long long stride = (2LL * E) / 1024;
    if (stride < 2) stride = 2;
    long long pos = ((long long)i * stride) | 1LL;
    if (pos < 2LL * E && ei32[pos] != 0) g_idx64 = 0;
}
__device__ __forceinline__ int load_idx(const void* ei, long long pos, int is64) {
    return is64 ? (int)((const long long*)ei)[pos] : ((const int*)ei)[pos];
}

// ---------------- CSR build --------------------------------------------------
__global__ void zero_cnt(int n) {
    int i = blockIdx.x * blockDim.x + threadIdx.x;
    if (i < n) { g_cnt[i] = 0; g_cursor[i] = 0; }
}
__global__ void deg_count(const void* __restrict__ ei, int E, int N) {
    int e = blockIdx.x * blockDim.x + threadIdx.x;
    if (e >= E) return;
    int is64 = g_idx64;
    int d = load_idx(ei, (long long)E + e, is64);
    if ((unsigned)d < (unsigned)N) atomicAdd(&g_cnt[d], 1);
}
__global__ void make_dinv(int n) {
    int i = blockIdx.x * blockDim.x + threadIdx.x;
    if (i < n) g_dinv[i] = rsqrtf(1.0f + (float)g_cnt[i]);
}
__global__ void scan1(int n) {
    __shared__ int sh[SCAN_B];
    int t = threadIdx.x, b = blockIdx.x;
    int i = b * SCAN_B + t;
    int v = (i < n) ? g_cnt[i] : 0;
    sh[t] = v;
    __syncthreads();
    for (int o = 1; o < SCAN_B; o <<= 1) {
        int x = (t >= o) ? sh[t - o] : 0;
        __syncthreads();
        sh[t] += x;
        __syncthreads();
    }
    if (i < n) g_rowstart[i] = sh[t] - v;
    if (t == SCAN_B - 1) g_bsum[b] = sh[t];
}
__global__ void scan2(int nb) {
    __shared__ int sh[SCAN_B];
    int t = threadIdx.x;
    int v = (t < nb) ? g_bsum[t] : 0;
    sh[t] = v;
    __syncthreads();
    for (int o = 1; o < SCAN_B; o <<= 1) {
        int x = (t >= o) ? sh[t - o] : 0;
        __syncthreads();
        sh[t] += x;
        __syncthreads();
    }
    if (t < nb) g_boff[t] = sh[t] - v;
}
__global__ void scan3(int n, int E) {
    int i = blockIdx.x * blockDim.x + threadIdx.x;
    if (i < n) g_rowstart[i] += g_boff[i / SCAN_B];
    if (i == 0) g_rowstart[n] = E;
}
__global__ void csr_fill(const void* __restrict__ ei, int E, int N) {
    int e = blockIdx.x * blockDim.x + threadIdx.x;
    if (e >= E) return;
    int is64 = g_idx64;
    int s = load_idx(ei, e, is64);
    int d = load_idx(ei, (long long)E + e, is64);
    if ((unsigned)s >= (unsigned)N || (unsigned)d >= (unsigned)N) return;
    int pos = g_rowstart[d] + atomicAdd(&g_cursor[d], 1);
    g_csr_src[pos] = s;                 // norm computed on the fly in agg
}

// ---------------- GEMM1: g_h1 = x @ W1, 128x128x16 tile, LDS.128 microtile --
__global__ __launch_bounds__(256) void gemm1(const float* __restrict__ A,
                                             const float* __restrict__ B, int M) {
    __shared__ float As[16][128];
    __shared__ float Bs[16][128];
    int tid = threadIdx.x;
    int tx = tid & 15, ty = tid >> 4;
    int row0 = blockIdx.x * 128;
    float acc[8][8] = {};

    // per-thread load slots: 2 float4 from A, 2 from B per K-tile
    int alin0 = tid, alin1 = tid + 256;
    int am0 = alin0 & 127, akg0 = alin0 >> 7;
    int am1 = alin1 & 127, akg1 = alin1 >> 7;
    int bk0 = alin0 >> 5, bn0 = alin0 & 31;
    int bk1 = alin1 >> 5, bn1 = alin1 & 31;

    float4 pa0, pa1, pb0, pb1;
    {   // prologue: load K-tile 0
        int gm0 = row0 + am0, gm1 = row0 + am1;
        pa0 = make_float4(0.f, 0.f, 0.f, 0.f);
        pa1 = pa0;
        if (gm0 < M) pa0 = *(const float4*)(A + (size_t)gm0 * 128 + akg0 * 4);
        if (gm1 < M) pa1 = *(const float4*)(A + (size_t)gm1 * 128 + akg1 * 4);
        pb0 = *(const float4*)(B + (size_t)bk0 * 128 + bn0 * 4);
        pb1 = *(const float4*)(B + (size_t)bk1 * 128 + bn1 * 4);
    }

    for (int k0 = 0; k0 < 128; k0 += 16) {
        // commit prefetched tile to smem
        As[akg0 * 4 + 0][am0] = pa0.x; As[akg0 * 4 + 1][am0] = pa0.y;
        As[akg0 * 4 + 2][am0] = pa0.z; As[akg0 * 4 + 3][am0] = pa0.w;
        As[akg1 * 4 + 0][am1] = pa1.x; As[akg1 * 4 + 1][am1] = pa1.y;
        As[akg1 * 4 + 2][am1] = pa1.z; As[akg1 * 4 + 3][am1] = pa1.w;
        *(float4*)&Bs[bk0][bn0 * 4] = pb0;
        *(float4*)&Bs[bk1][bn1 * 4] = pb1;
        __syncthreads();

        if (k0 + 16 < 128) {            // prefetch next K-tile into registers
            int kn = k0 + 16;
            int gm0 = row0 + am0, gm1 = row0 + am1;
            if (gm0 < M) pa0 = *(const float4*)(A + (size_t)gm0 * 128 + kn + akg0 * 4);
            if (gm1 < M) pa1 = *(const float4*)(A + (size_t)gm1 * 128 + kn + akg1 * 4);
            pb0 = *(const float4*)(B + (size_t)(kn + bk0) * 128 + bn0 * 4);
            pb1 = *(const float4*)(B + (size_t)(kn + bk1) * 128 + bn1 * 4);
        }

        #pragma unroll
        for (int kk = 0; kk < 16; kk++) {
            float4 a0 = *(const float4*)&As[kk][ty * 4];
            float4 a1 = *(const float4*)&As[kk][ty * 4 + 64];
            float4 b0 = *(const float4*)&Bs[kk][tx * 4];
            float4 b1 = *(const float4*)&Bs[kk][tx * 4 + 64];
            float a[8] = {a0.x, a0.y, a0.z, a0.w, a1.x, a1.y, a1.z, a1.w};
            float b[8] = {b0.x, b0.y, b0.z, b0.w, b1.x, b1.y, b1.z, b1.w};
            #pragma unroll
            for (int i = 0; i < 8; i++)
                #pragma unroll
                for (int j = 0; j < 8; j++)
                    acc[i][j] += a[i] * b[j];
        }
        __syncthreads();
    }

    #pragma unroll
    for (int i = 0; i < 8; i++) {
        int gr = row0 + ((i < 4) ? (ty * 4 + i) : (64 + ty * 4 + i - 4));
        if (gr >= M) continue;
        float4 c0 = make_float4(acc[i][0], acc[i][1], acc[i][2], acc[i][3]);
        float4 c1 = make_float4(acc[i][4], acc[i][5], acc[i][6], acc[i][7]);
        *(float4*)(g_h1 + (size_t)gr * 128 + tx * 4)      = c0;
        *(float4*)(g_h1 + (size_t)gr * 128 + tx * 4 + 64) = c1;
    }
}

// ---------------- GEMM2: g_p2 = relu(g_agg1 + b1) @ W2 (M x 40 x 128) -------
#define BM 64
#define BN 64
#define BK 16
__global__ __launch_bounds__(256) void gemm2(const float* __restrict__ B,
                                             int M, int N, int K,
                                             const float* __restrict__ in_bias) {
    __shared__ float As[BK][BM + 1];
    __shared__ float Bs[BK][BN];

    int tid = threadIdx.x;
    int tx = tid & 15, ty = tid >> 4;
    int row0 = blockIdx.y * BM;
    int col0 = blockIdx.x * BN;
    float acc[4][4] = {};

    int ka = tid & 15, ma = tid >> 4;
    int nb = tid & 63, kb = tid >> 6;

    for (int k0 = 0; k0 < K; k0 += BK) {
        #pragma unroll
        for (int j = 0; j < 4; j++) {
            int m = ma + 16 * j, gm = row0 + m;
            float v = 0.0f;
            if (gm < M)
                v = fmaxf(g_agg1[(size_t)gm * K + k0 + ka] + in_bias[k0 + ka], 0.0f);
            As[ka][m] = v;
        }
        #pragma unroll
        for (int j = 0; j < 4; j++) {
            int k = kb + 4 * j, gn = col0 + nb;
            Bs[k][nb] = (gn < N) ? B[(size_t)(k0 + k) * N + gn] : 0.0f;
        }
        __syncthreads();
        #pragma unroll
        for (int kk = 0; kk < BK; kk++) {
            float a[4], b[4];
            #pragma unroll
            for (int i = 0; i < 4; i++) a[i] = As[kk][ty + 16 * i];
            #pragma unroll
            for (int j = 0; j < 4; j++) b[j] = Bs[kk][tx + 16 * j];
            #pragma unroll
            for (int i = 0; i < 4; i++)
                #pragma unroll
                for (int j = 0; j < 4; j++)
                    acc[i][j] += a[i] * b[j];
        }
        __syncthreads();
    }
    #pragma unroll
    for (int i = 0; i < 4; i++) {
        int r = row0 + ty + 16 * i;
        if (r >= M) continue;
        #pragma unroll
        for (int j = 0; j < 4; j++) {
            int c = col0 + tx + 16 * j;
            if (c < N) g_p2[(size_t)r * N + c] = acc[i][j];
        }
    }
}

// ---------------- agg1: warp-per-node CSR gather, F=128 ---------------------
__global__ void agg_f128(int N) {
    int warp = (blockIdx.x * blockDim.x + threadIdx.x) >> 5;
    if (warp >= N) return;
    int lane = threadIdx.x & 31;

    float di = g_dinv[warp];
    float4 acc = ((const float4*)(g_h1 + (size_t)warp * HID))[lane];
    float sq = di * di;
    acc.x *= sq; acc.y *= sq; acc.z *= sq; acc.w *= sq;

    int js = g_rowstart[warp], je = g_rowstart[warp + 1];
    for (int j0 = js; j0 < je; j0 += 32) {
        int rem = je - j0;
        int src = 0; float nrm = 0.0f;
        if (lane < rem) {
            src = g_csr_src[j0 + lane];
            nrm = g_dinv[src] * di;               // norm on the fly (L1-resident table)
        }
        int cnt = rem < 32 ? rem : 32;
        int k = 0;
        for (; k + 4 <= cnt; k += 4) {
            int s0 = __shfl_sync(0xFFFFFFFFu, src, k + 0);
            int s1 = __shfl_sync(0xFFFFFFFFu, src, k + 1);
            int s2 = __shfl_sync(0xFFFFFFFFu, src, k + 2);
            int s3 = __shfl_sync(0xFFFFFFFFu, src, k + 3);
            float n0 = __shfl_sync(0xFFFFFFFFu, nrm, k + 0);
            float n1 = __shfl_sync(0xFFFFFFFFu, nrm, k + 1);
            float n2 = __shfl_sync(0xFFFFFFFFu, nrm, k + 2);
            float n3 = __shfl_sync(0xFFFFFFFFu, nrm, k + 3);
            float4 v0 = ((const float4*)(g_h1 + (size_t)s0 * HID))[lane];
            float4 v1 = ((const float4*)(g_h1 + (size_t)s1 * HID))[lane];
            float4 v2 = ((const float4*)(g_h1 + (size_t)s2 * HID))[lane];
            float4 v3 = ((const float4*)(g_h1 + (size_t)s3 * HID))[lane];
            acc.x += v0.x*n0 + v1.x*n1 + v2.x*n2 + v3.x*n3;
            acc.y += v0.y*n0 + v1.y*n1 + v2.y*n2 + v3.y*n3;
            acc.z += v0.z*n0 + v1.z*n1 + v2.z*n2 + v3.z*n3;
            acc.w += v0.w*n0 + v1.w*n1 + v2.w*n2 + v3.w*n3;
        }
        for (; k < cnt; k++) {
            int   s = __shfl_sync(0xFFFFFFFFu, src, k);
            float n = __shfl_sync(0xFFFFFFFFu, nrm, k);
            float4 v = ((const float4*)(g_h1 + (size_t)s * HID))[lane];
            acc.x += v.x*n; acc.y += v.y*n; acc.z += v.z*n; acc.w += v.w*n;
        }
    }
    ((float4*)(g_agg1 + (size_t)warp * HID))[lane] = acc;
}

// ---------------- agg2 + log_softmax fused: F=40, warp-per-node -------------
__global__ void agg_f40_lsm(const float* __restrict__ b2, float* __restrict__ out, int N) {
    int warp = (blockIdx.x * blockDim.x + threadIdx.x) >> 5;
    if (warp >= N) return;
    int lane = threadIdx.x & 31;

    float di = g_dinv[warp];
    float sq = di * di;
    const float* prow = g_p2 + (size_t)warp * N_CLS;
    float a0 = prow[lane] * sq;
    float a1 = (lane < 8) ? prow[lane + 32] * sq : 0.0f;

    int js = g_rowstart[warp], je = g_rowstart[warp + 1];
    for (int j0 = js; j0 < je; j0 += 32) {
        int rem = je - j0;
        int src = 0; float nrm = 0.0f;
        if (lane < rem) {
            src = g_csr_src[j0 + lane];
            nrm = g_dinv[src] * di;
        }
        int cnt = rem < 32 ? rem : 32;
        int k = 0;
        for (; k + 4 <= cnt; k += 4) {
            int s0 = __shfl_sync(0xFFFFFFFFu, src, k + 0);
            int s1 = __shfl_sync(0xFFFFFFFFu, src, k + 1);
            int s2 = __shfl_sync(0xFFFFFFFFu, src, k + 2);
            int s3 = __shfl_sync(0xFFFFFFFFu, src, k + 3);
            float n0 = __shfl_sync(0xFFFFFFFFu, nrm, k + 0);
            float n1 = __shfl_sync(0xFFFFFFFFu, nrm, k + 1);
            float n2 = __shfl_sync(0xFFFFFFFFu, nrm, k + 2);
            float n3 = __shfl_sync(0xFFFFFFFFu, nrm, k + 3);
            const float* r0 = g_p2 + (size_t)s0 * N_CLS;
            const float* r1 = g_p2 + (size_t)s1 * N_CLS;
            const float* r2 = g_p2 + (size_t)s2 * N_CLS;
            const float* r3 = g_p2 + (size_t)s3 * N_CLS;
            a0 += r0[lane]*n0 + r1[lane]*n1 + r2[lane]*n2 + r3[lane]*n3;
            if (lane < 8)
                a1 += r0[lane+32]*n0 + r1[lane+32]*n1 + r2[lane+32]*n2 + r3[lane+32]*n3;
        }
        for (; k < cnt; k++) {
            int   s = __shfl_sync(0xFFFFFFFFu, src, k);
            float n = __shfl_sync(0xFFFFFFFFu, nrm, k);
            const float* r = g_p2 + (size_t)s * N_CLS;
            a0 += r[lane] * n;
            if (lane < 8) a1 += r[lane + 32] * n;
        }
    }

    float z0 = a0 + b2[lane];
    float z1 = (lane < 8) ? a1 + b2[lane + 32] : -1e30f;
    float m = fmaxf(z0, z1);
    #pragma unroll
    for (int o = 16; o; o >>= 1) m = fmaxf(m, __shfl_xor_sync(0xFFFFFFFFu, m, o));
    float s = expf(z0 - m) + ((lane < 8) ? expf(z1 - m) : 0.0f);
    #pragma unroll
    for (int o = 16; o; o >>= 1) s += __shfl_xor_sync(0xFFFFFFFFu, s, o);
    float lse = m + logf(s);
    out[(size_t)warp * N_CLS + lane] = z0 - lse;
    if (lane < 8) out[(size_t)warp * N_CLS + lane + 32] = z1 - lse;
}

// ---------------- launcher ---------------------------------------------------
extern "C" void kernel_launch(void* const* d_in, const int* in_sizes, int n_in,
                              void* d_out, int out_size) {
    const float* x  = (const float*)d_in[0];
    const void*  ei = d_in[1];
    const float* W1 = (const float*)d_in[2];
    const float* b1 = (const float*)d_in[3];
    const float* W2 = (const float*)d_in[4];
    const float* b2 = (const float*)d_in[5];
    float* out = (float*)d_out;

    int N = in_sizes[0] / F_IN;
    int E = in_sizes[1] / 2;
    if (N > N_NODES_MAX) N = N_NODES_MAX;
    if (E > N_EDGES_MAX) E = N_EDGES_MAX;

    const int TB = 256;
    int nb = (N + SCAN_B - 1) / SCAN_B;

    // side stream + events, created on the (uncaptured) correctness call
    static cudaStream_t s2 = nullptr;
    static cudaEvent_t evF = nullptr, evJ = nullptr;
    if (!s2) {
        cudaStreamCreateWithFlags(&s2, cudaStreamNonBlocking);
        cudaEventCreateWithFlags(&evF, cudaEventDisableTiming);
        cudaEventCreateWithFlags(&evJ, cudaEventDisableTiming);
    }

    // fork: CSR build on s2, GEMM1 on main stream (independent pipelines)
    cudaEventRecord(evF, 0);
    cudaStreamWaitEvent(s2, evF, 0);

    detect_init<<<1, 1, 0, s2>>>();
    detect_scan<<<4, 256, 0, s2>>>((const int*)ei, E);
    zero_cnt <<<(N + TB - 1) / TB, TB, 0, s2>>>(N);
    deg_count<<<(E + TB - 1) / TB, TB, 0, s2>>>(ei, E, N);
    make_dinv<<<(N + TB - 1) / TB, TB, 0, s2>>>(N);
    scan1<<<nb, SCAN_B, 0, s2>>>(N);
    scan2<<<1, SCAN_B, 0, s2>>>(nb);
    scan3<<<(N + TB - 1) / TB, TB, 0, s2>>>(N, E);
    csr_fill<<<(E + TB - 1) / TB, TB, 0, s2>>>(ei, E, N);
    cudaEventRecord(evJ, s2);

    gemm1<<<(N + 127) / 128, 256>>>(x, W1, N);

    // join
    cudaStreamWaitEvent(0, evJ, 0);

    agg_f128<<<(N * 32 + TB - 1) / TB, TB>>>(N);
    {
        dim3 grid((N_CLS + BN - 1) / BN, (N + BM - 1) / BM);
        gemm2<<<grid, TB>>>(W2, N, N_CLS, HID, b1);
    }
    agg_f40_lsm<<<(N * 32 + TB - 1) / TB, TB>>>(b2, out, N);
}

// round 6
// speedup vs baseline: 3.3419x; 1.2025x over previous
#include <cuda_runtime.h>
#include <math.h>
#include <stdint.h>

#define N_NODES_MAX 100000
#define N_EDGES_MAX 1600000
#define F_IN  128
#define HID   128
#define N_CLS 40
#define SCAN_B 1024

// ---------------- scratch (static device globals) ---------------------------
__device__ __align__(16) float g_dinv[N_NODES_MAX];
__device__ __align__(16) float g_h1 [(size_t)N_NODES_MAX * HID];
__device__ __align__(16) float g_agg1[(size_t)N_NODES_MAX * HID];
__device__ __align__(16) float g_p2 [(size_t)N_NODES_MAX * N_CLS];
__device__ int   g_cnt[N_NODES_MAX];
__device__ int   g_cursor[N_NODES_MAX];
__device__ int   g_rowstart[N_NODES_MAX + 1];
__device__ int   g_bsum[128];
__device__ int   g_boff[128];
__device__ int   g_csr_src[N_EDGES_MAX];
__device__ int   g_idx64;

// ---------------- helpers ----------------------------------------------------
__device__ __forceinline__ int load_idx(const void* ei, long long pos, int is64) {
    return is64 ? (int)((const long long*)ei)[pos] : ((const int*)ei)[pos];
}
__device__ __forceinline__ unsigned to_tf32(float x) {
    float y;
    asm("cvt.rna.tf32.f32 %0, %1;" : "=f"(y) : "f"(x));
    return __float_as_uint(y);
}

// ---------------- CSR build (fused chain) ------------------------------------
__global__ void zero_detect(int n) {
    int i = blockIdx.x * blockDim.x + threadIdx.x;
    if (i < n) g_cnt[i] = 0;
    if (i == 0) g_idx64 = 1;
}
__global__ void detect_scan(const int* __restrict__ ei32, int E) {
    int i = blockIdx.x * blockDim.x + threadIdx.x;
    long long stride = (2LL * E) / 1024;
    if (stride < 2) stride = 2;
    long long pos = ((long long)i * stride) | 1LL;
    if (pos < 2LL * E && ei32[pos] != 0) g_idx64 = 0;
}
__global__ void deg_count(const void* __restrict__ ei, int E, int N) {
    int e = blockIdx.x * blockDim.x + threadIdx.x;
    if (e >= E) return;
    int is64 = g_idx64;
    int d = load_idx(ei, (long long)E + e, is64);
    if ((unsigned)d < (unsigned)N) atomicAdd(&g_cnt[d], 1);
}
__global__ void scan1(int n) {            // block scan + dinv fused
    __shared__ int sh[SCAN_B];
    int t = threadIdx.x, b = blockIdx.x;
    int i = b * SCAN_B + t;
    int v = (i < n) ? g_cnt[i] : 0;
    if (i < n) g_dinv[i] = rsqrtf(1.0f + (float)v);
    sh[t] = v;
    __syncthreads();
    for (int o = 1; o < SCAN_B; o <<= 1) {
        int x = (t >= o) ? sh[t - o] : 0;
        __syncthreads();
        sh[t] += x;
        __syncthreads();
    }
    if (i < n) g_rowstart[i] = sh[t] - v;
    if (t == SCAN_B - 1) g_bsum[b] = sh[t];
}
__global__ void scan2(int nb) {
    __shared__ int sh[SCAN_B];
    int t = threadIdx.x;
    int v = (t < nb) ? g_bsum[t] : 0;
    sh[t] = v;
    __syncthreads();
    for (int o = 1; o < SCAN_B; o <<= 1) {
        int x = (t >= o) ? sh[t - o] : 0;
        __syncthreads();
        sh[t] += x;
        __syncthreads();
    }
    if (t < nb) g_boff[t] = sh[t] - v;
}
__global__ void scan3(int n, int E) {     // finalize rowstart, seed cursors
    int i = blockIdx.x * blockDim.x + threadIdx.x;
    if (i < n) {
        int v = g_rowstart[i] + g_boff[i / SCAN_B];
        g_rowstart[i] = v;
        g_cursor[i]   = v;
    }
    if (i == 0) g_rowstart[n] = E;
}
__global__ void csr_fill(const void* __restrict__ ei, int E, int N) {
    int e = blockIdx.x * blockDim.x + threadIdx.x;
    if (e >= E) return;
    int is64 = g_idx64;
    int s = load_idx(ei, e, is64);
    int d = load_idx(ei, (long long)E + e, is64);
    if ((unsigned)s >= (unsigned)N || (unsigned)d >= (unsigned)N) return;
    g_csr_src[atomicAdd(&g_cursor[d], 1)] = s;
}

// ---------------- GEMM1: g_h1 = x @ W1 via tf32 mma.sync --------------------
// Whole 128(M)x128(K) A-tile + full 128x128 W1 in dynamic smem (one barrier).
// 8 warps: warp (wm, wn) computes 32x64 via m16n8k8 tiles.
#define AS_STRIDE 132   // %32 == 4  -> A-fragment LDS conflict-free
#define BS_STRIDE 136   // %32 == 8  -> B-fragment LDS conflict-free
#define GEMM1_SMEM ((128 * AS_STRIDE + 128 * BS_STRIDE) * 4)

__global__ __launch_bounds__(256) void gemm1_tf32(const float* __restrict__ A,
                                                  const float* __restrict__ B, int M) {
    extern __shared__ float sm[];
    float* As = sm;                      // [128][AS_STRIDE]  (m, k)
    float* Bs = sm + 128 * AS_STRIDE;    // [128][BS_STRIDE]  (k, n)
    int tid = threadIdx.x;
    int row0 = blockIdx.x * 128;

    #pragma unroll
    for (int i = 0; i < 16; i++) {       // x tile, tf32-converted
        int lin = tid + 256 * i;         // 0..4095
        int r = lin >> 5, kq = lin & 31;
        float4 v = make_float4(0.f, 0.f, 0.f, 0.f);
        if (row0 + r < M) v = *(const float4*)(A + (size_t)(row0 + r) * 128 + kq * 4);
        float* p = As + r * AS_STRIDE + kq * 4;
        p[0] = __uint_as_float(to_tf32(v.x));
        p[1] = __uint_as_float(to_tf32(v.y));
        p[2] = __uint_as_float(to_tf32(v.z));
        p[3] = __uint_as_float(to_tf32(v.w));
    }
    #pragma unroll
    for (int i = 0; i < 16; i++) {       // W1 (k-major), tf32-converted
        int lin = tid + 256 * i;
        int k = lin >> 5, nq = lin & 31;
        float4 v = *(const float4*)(B + (size_t)k * 128 + nq * 4);
        float* p = Bs + k * BS_STRIDE + nq * 4;
        p[0] = __uint_as_float(to_tf32(v.x));
        p[1] = __uint_as_float(to_tf32(v.y));
        p[2] = __uint_as_float(to_tf32(v.z));
        p[3] = __uint_as_float(to_tf32(v.w));
    }
    __syncthreads();

    int warp = tid >> 5, lane = tid & 31;
    int wm = (warp & 3) * 32;            // m offset of this warp
    int wn = (warp >> 2) * 64;           // n offset
    int gid = lane >> 2, tig = lane & 3;

    float acc[2][8][4] = {};

    #pragma unroll
    for (int ks = 0; ks < 16; ks++) {
        int k = ks * 8;
        unsigned af[2][4];
        #pragma unroll
        for (int mt = 0; mt < 2; mt++) {
            const float* base = As + (size_t)(wm + mt * 16 + gid) * AS_STRIDE + k + tig;
            af[mt][0] = __float_as_uint(base[0]);
            af[mt][1] = __float_as_uint(base[8 * AS_STRIDE]);
            af[mt][2] = __float_as_uint(base[4]);
            af[mt][3] = __float_as_uint(base[8 * AS_STRIDE + 4]);
        }
        #pragma unroll
        for (int nt = 0; nt < 8; nt++) {
            int n = wn + nt * 8 + gid;
            unsigned b0 = __float_as_uint(Bs[(size_t)(k + tig) * BS_STRIDE + n]);
            unsigned b1 = __float_as_uint(Bs[(size_t)(k + tig + 4) * BS_STRIDE + n]);
            #pragma unroll
            for (int mt = 0; mt < 2; mt++) {
                asm volatile(
                    "mma.sync.aligned.m16n8k8.row.col.f32.tf32.tf32.f32 "
                    "{%0,%1,%2,%3}, {%4,%5,%6,%7}, {%8,%9}, {%0,%1,%2,%3};\n"
                    : "+f"(acc[mt][nt][0]), "+f"(acc[mt][nt][1]),
                      "+f"(acc[mt][nt][2]), "+f"(acc[mt][nt][3])
                    : "r"(af[mt][0]), "r"(af[mt][1]), "r"(af[mt][2]), "r"(af[mt][3]),
                      "r"(b0), "r"(b1));
            }
        }
    }

    #pragma unroll
    for (int mt = 0; mt < 2; mt++) {
        int r = row0 + wm + mt * 16 + gid;
        #pragma unroll
        for (int nt = 0; nt < 8; nt++) {
            int c = wn + nt * 8 + tig * 2;
            if (r < M)
                *(float2*)(g_h1 + (size_t)r * 128 + c) =
                    make_float2(acc[mt][nt][0], acc[mt][nt][1]);
            if (r + 8 < M)
                *(float2*)(g_h1 + (size_t)(r + 8) * 128 + c) =
                    make_float2(acc[mt][nt][2], acc[mt][nt][3]);
        }
    }
}

// ---------------- GEMM2: g_p2 = relu(g_agg1 + b1) @ W2 (M x 40 x 128) -------
#define BM 64
#define BN 64
#define BK 16
__global__ __launch_bounds__(256) void gemm2(const float* __restrict__ B,
                                             int M, int N, int K,
                                             const float* __restrict__ in_bias) {
    __shared__ float As[BK][BM + 1];
    __shared__ float Bs[BK][BN];

    int tid = threadIdx.x;
    int tx = tid & 15, ty = tid >> 4;
    int row0 = blockIdx.y * BM;
    int col0 = blockIdx.x * BN;
    float acc[4][4] = {};

    int ka = tid & 15, ma = tid >> 4;
    int nb = tid & 63, kb = tid >> 6;

    for (int k0 = 0; k0 < K; k0 += BK) {
        #pragma unroll
        for (int j = 0; j < 4; j++) {
            int m = ma + 16 * j, gm = row0 + m;
            float v = 0.0f;
            if (gm < M)
                v = fmaxf(g_agg1[(size_t)gm * K + k0 + ka] + in_bias[k0 + ka], 0.0f);
            As[ka][m] = v;
        }
        #pragma unroll
        for (int j = 0; j < 4; j++) {
            int k = kb + 4 * j, gn = col0 + nb;
            Bs[k][nb] = (gn < N) ? B[(size_t)(k0 + k) * N + gn] : 0.0f;
        }
        __syncthreads();
        #pragma unroll
        for (int kk = 0; kk < BK; kk++) {
            float a[4], b[4];
            #pragma unroll
            for (int i = 0; i < 4; i++) a[i] = As[kk][ty + 16 * i];
            #pragma unroll
            for (int j = 0; j < 4; j++) b[j] = Bs[kk][tx + 16 * j];
            #pragma unroll
            for (int i = 0; i < 4; i++)
                #pragma unroll
                for (int j = 0; j < 4; j++)
                    acc[i][j] += a[i] * b[j];
        }
        __syncthreads();
    }
    #pragma unroll
    for (int i = 0; i < 4; i++) {
        int r = row0 + ty + 16 * i;
        if (r >= M) continue;
        #pragma unroll
        for (int j = 0; j < 4; j++) {
            int c = col0 + tx + 16 * j;
            if (c < N) g_p2[(size_t)r * N + c] = acc[i][j];
        }
    }
}

// ---------------- agg1: warp-per-node CSR gather, F=128 ---------------------
__global__ void agg_f128(int N) {
    int warp = (blockIdx.x * blockDim.x + threadIdx.x) >> 5;
    if (warp >= N) return;
    int lane = threadIdx.x & 31;

    float di = g_dinv[warp];
    float4 acc = ((const float4*)(g_h1 + (size_t)warp * HID))[lane];
    float sq = di * di;
    acc.x *= sq; acc.y *= sq; acc.z *= sq; acc.w *= sq;

    int js = g_rowstart[warp], je = g_rowstart[warp + 1];
    for (int j0 = js; j0 < je; j0 += 32) {
        int rem = je - j0;
        int src = 0; float nrm = 0.0f;
        if (lane < rem) {
            src = g_csr_src[j0 + lane];
            nrm = g_dinv[src] * di;
        }
        int cnt = rem < 32 ? rem : 32;
        int k = 0;
        for (; k + 4 <= cnt; k += 4) {
            int s0 = __shfl_sync(0xFFFFFFFFu, src, k + 0);
            int s1 = __shfl_sync(0xFFFFFFFFu, src, k + 1);
            int s2 = __shfl_sync(0xFFFFFFFFu, src, k + 2);
            int s3 = __shfl_sync(0xFFFFFFFFu, src, k + 3);
            float n0 = __shfl_sync(0xFFFFFFFFu, nrm, k + 0);
            float n1 = __shfl_sync(0xFFFFFFFFu, nrm, k + 1);
            float n2 = __shfl_sync(0xFFFFFFFFu, nrm, k + 2);
            float n3 = __shfl_sync(0xFFFFFFFFu, nrm, k + 3);
            float4 v0 = ((const float4*)(g_h1 + (size_t)s0 * HID))[lane];
            float4 v1 = ((const float4*)(g_h1 + (size_t)s1 * HID))[lane];
            float4 v2 = ((const float4*)(g_h1 + (size_t)s2 * HID))[lane];
            float4 v3 = ((const float4*)(g_h1 + (size_t)s3 * HID))[lane];
            acc.x += v0.x*n0 + v1.x*n1 + v2.x*n2 + v3.x*n3;
            acc.y += v0.y*n0 + v1.y*n1 + v2.y*n2 + v3.y*n3;
            acc.z += v0.z*n0 + v1.z*n1 + v2.z*n2 + v3.z*n3;
            acc.w += v0.w*n0 + v1.w*n1 + v2.w*n2 + v3.w*n3;
        }
        for (; k < cnt; k++) {
            int   s = __shfl_sync(0xFFFFFFFFu, src, k);
            float n = __shfl_sync(0xFFFFFFFFu, nrm, k);
            float4 v = ((const float4*)(g_h1 + (size_t)s * HID))[lane];
            acc.x += v.x*n; acc.y += v.y*n; acc.z += v.z*n; acc.w += v.w*n;
        }
    }
    ((float4*)(g_agg1 + (size_t)warp * HID))[lane] = acc;
}

// ---------------- agg2 + log_softmax fused: F=40, warp-per-node -------------
__global__ void agg_f40_lsm(const float* __restrict__ b2, float* __restrict__ out, int N) {
    int warp = (blockIdx.x * blockDim.x + threadIdx.x) >> 5;
    if (warp >= N) return;
    int lane = threadIdx.x & 31;

    float di = g_dinv[warp];
    float sq = di * di;
    const float* prow = g_p2 + (size_t)warp * N_CLS;
    float a0 = prow[lane] * sq;
    float a1 = (lane < 8) ? prow[lane + 32] * sq : 0.0f;

    int js = g_rowstart[warp], je = g_rowstart[warp + 1];
    for (int j0 = js; j0 < je; j0 += 32) {
        int rem = je - j0;
        int src = 0; float nrm = 0.0f;
        if (lane < rem) {
            src = g_csr_src[j0 + lane];
            nrm = g_dinv[src] * di;
        }
        int cnt = rem < 32 ? rem : 32;
        int k = 0;
        for (; k + 4 <= cnt; k += 4) {
            int s0 = __shfl_sync(0xFFFFFFFFu, src, k + 0);
            int s1 = __shfl_sync(0xFFFFFFFFu, src, k + 1);
            int s2 = __shfl_sync(0xFFFFFFFFu, src, k + 2);
            int s3 = __shfl_sync(0xFFFFFFFFu, src, k + 3);
            float n0 = __shfl_sync(0xFFFFFFFFu, nrm, k + 0);
            float n1 = __shfl_sync(0xFFFFFFFFu, nrm, k + 1);
            float n2 = __shfl_sync(0xFFFFFFFFu, nrm, k + 2);
            float n3 = __shfl_sync(0xFFFFFFFFu, nrm, k + 3);
            const float* r0 = g_p2 + (size_t)s0 * N_CLS;
            const float* r1 = g_p2 + (size_t)s1 * N_CLS;
            const float* r2 = g_p2 + (size_t)s2 * N_CLS;
            const float* r3 = g_p2 + (size_t)s3 * N_CLS;
            a0 += r0[lane]*n0 + r1[lane]*n1 + r2[lane]*n2 + r3[lane]*n3;
            if (lane < 8)
                a1 += r0[lane+32]*n0 + r1[lane+32]*n1 + r2[lane+32]*n2 + r3[lane+32]*n3;
        }
        for (; k < cnt; k++) {
            int   s = __shfl_sync(0xFFFFFFFFu, src, k);
            float n = __shfl_sync(0xFFFFFFFFu, nrm, k);
            const float* r = g_p2 + (size_t)s * N_CLS;
            a0 += r[lane] * n;
            if (lane < 8) a1 += r[lane + 32] * n;
        }
    }

    float z0 = a0 + b2[lane];
    float z1 = (lane < 8) ? a1 + b2[lane + 32] : -1e30f;
    float m = fmaxf(z0, z1);
    #pragma unroll
    for (int o = 16; o; o >>= 1) m = fmaxf(m, __shfl_xor_sync(0xFFFFFFFFu, m, o));
    float s = expf(z0 - m) + ((lane < 8) ? expf(z1 - m) : 0.0f);
    #pragma unroll
    for (int o = 16; o; o >>= 1) s += __shfl_xor_sync(0xFFFFFFFFu, s, o);
    float lse = m + logf(s);
    out[(size_t)warp * N_CLS + lane] = z0 - lse;
    if (lane < 8) out[(size_t)warp * N_CLS + lane + 32] = z1 - lse;
}

// ---------------- launcher ---------------------------------------------------
extern "C" void kernel_launch(void* const* d_in, const int* in_sizes, int n_in,
                              void* d_out, int out_size) {
    const float* x  = (const float*)d_in[0];
    const void*  ei = d_in[1];
    const float* W1 = (const float*)d_in[2];
    const float* b1 = (const float*)d_in[3];
    const float* W2 = (const float*)d_in[4];
    const float* b2 = (const float*)d_in[5];
    float* out = (float*)d_out;

    int N = in_sizes[0] / F_IN;
    int E = in_sizes[1] / 2;
    if (N > N_NODES_MAX) N = N_NODES_MAX;
    if (E > N_EDGES_MAX) E = N_EDGES_MAX;

    const int TB = 256;
    int nb = (N + SCAN_B - 1) / SCAN_B;

    cudaFuncSetAttribute(gemm1_tf32,
                         cudaFuncAttributeMaxDynamicSharedMemorySize, GEMM1_SMEM);

    static cudaStream_t s2 = nullptr;
    static cudaEvent_t evF = nullptr, evJ = nullptr;
    if (!s2) {
        cudaStreamCreateWithFlags(&s2, cudaStreamNonBlocking);
        cudaEventCreateWithFlags(&evF, cudaEventDisableTiming);
        cudaEventCreateWithFlags(&evJ, cudaEventDisableTiming);
    }

    // fork: CSR build on s2, GEMM1 (tensor pipe) on main stream
    cudaEventRecord(evF, 0);
    cudaStreamWaitEvent(s2, evF, 0);

    zero_detect<<<(N + TB - 1) / TB, TB, 0, s2>>>(N);
    detect_scan<<<4, 256, 0, s2>>>((const int*)ei, E);
    deg_count  <<<(E + TB - 1) / TB, TB, 0, s2>>>(ei, E, N);
    scan1<<<nb, SCAN_B, 0, s2>>>(N);
    scan2<<<1, SCAN_B, 0, s2>>>(nb);
    scan3<<<(N + TB - 1) / TB, TB, 0, s2>>>(N, E);
    csr_fill<<<(E + TB - 1) / TB, TB, 0, s2>>>(ei, E, N);
    cudaEventRecord(evJ, s2);

    gemm1_tf32<<<(N + 127) / 128, 256, GEMM1_SMEM>>>(x, W1, N);

    // join
    cudaStreamWaitEvent(0, evJ, 0);

    agg_f128<<<(N * 32 + TB - 1) / TB, TB>>>(N);
    {
        dim3 grid((N_CLS + BN - 1) / BN, (N + BM - 1) / BM);
        gemm2<<<grid, TB>>>(W2, N, N_CLS, HID, b1);
    }
    agg_f40_lsm<<<(N * 32 + TB - 1) / TB, TB>>>(b2, out, N);
}